// round 1
// baseline (speedup 1.0000x reference)
#include <cuda_runtime.h>

#define BB 4
#define SS 2048
#define NH 16
#define HD 64
#define DM 1024

// Scratch for Q/K/V in [B, H, S, hd] layout (device globals: allocation-free).
__device__ float g_q[BB * NH * SS * HD];
__device__ float g_k[BB * NH * SS * HD];
__device__ float g_v[BB * NH * SS * HD];

// ---------------------------------------------------------------------------
// Kernel 1: fused QKV projection.
// out[t][c] = sum_d x[t][d] * W[c][d] + bias[c]  for W in {Wq, Wk, Wv}
// Combined column space 3*1024 = 3072. Block computes a 64x64 tile (one head's
// 64 dims -> contiguous float4 stores into [B,H,S,hd] scratch).
// ---------------------------------------------------------------------------
__global__ __launch_bounds__(256) void qkv_kernel(
    const float* __restrict__ x,
    const float* __restrict__ Wq, const float* __restrict__ bq,
    const float* __restrict__ Wk, const float* __restrict__ bk,
    const float* __restrict__ Wv, const float* __restrict__ bv)
{
    __shared__ float As[16][64];   // [k][row]
    __shared__ float Bs[16][64];   // [k][col]

    const int tid = threadIdx.x;
    const int tx = tid & 15;        // 0..15  (output cols, 4 each)
    const int ty = tid >> 4;        // 0..15  (output rows, 4 each)

    const int rowBase = blockIdx.y * 64;      // token rows
    const int colBase = blockIdx.x * 64;      // combined cols [0,3072)
    const int mat = colBase / DM;             // 0=Q 1=K 2=V
    const int colInMat = colBase % DM;

    const float* W    = (mat == 0) ? Wq : (mat == 1) ? Wk : Wv;
    const float* bias = (mat == 0) ? bq : (mat == 1) ? bk : bv;
    float*       dst  = (mat == 0) ? g_q : (mat == 1) ? g_k : g_v;

    const int lr = tid >> 2;        // 0..63 : row within tile to load
    const int lk = (tid & 3) * 4;   // 0,4,8,12 : k-chunk

    float acc[4][4] = {};

    for (int kt = 0; kt < DM; kt += 16) {
        float4 a = *(const float4*)&x[(size_t)(rowBase + lr) * DM + kt + lk];
        float4 w = *(const float4*)&W[(size_t)(colInMat + lr) * DM + kt + lk];
        As[lk + 0][lr] = a.x; As[lk + 1][lr] = a.y;
        As[lk + 2][lr] = a.z; As[lk + 3][lr] = a.w;
        Bs[lk + 0][lr] = w.x; Bs[lk + 1][lr] = w.y;
        Bs[lk + 2][lr] = w.z; Bs[lk + 3][lr] = w.w;
        __syncthreads();

        #pragma unroll
        for (int k = 0; k < 16; k++) {
            float4 av = *(const float4*)&As[k][ty * 4];
            float4 bv4 = *(const float4*)&Bs[k][tx * 4];
            float aa[4] = {av.x, av.y, av.z, av.w};
            float bb[4] = {bv4.x, bv4.y, bv4.z, bv4.w};
            #pragma unroll
            for (int i = 0; i < 4; i++)
                #pragma unroll
                for (int j = 0; j < 4; j++)
                    acc[i][j] += aa[i] * bb[j];
        }
        __syncthreads();
    }

    // Epilogue: add bias, scatter into [B,H,S,hd] (contiguous over hd -> float4).
    const int hh = colInMat / HD;   // head for this whole block
    const int d0 = tx * 4;
    float b0 = bias[colInMat + d0 + 0];
    float b1 = bias[colInMat + d0 + 1];
    float b2 = bias[colInMat + d0 + 2];
    float b3 = bias[colInMat + d0 + 3];

    #pragma unroll
    for (int i = 0; i < 4; i++) {
        int token = rowBase + ty * 4 + i;
        int bidx = token / SS;
        int s    = token % SS;
        float4 o;
        o.x = acc[i][0] + b0;
        o.y = acc[i][1] + b1;
        o.z = acc[i][2] + b2;
        o.w = acc[i][3] + b3;
        *(float4*)&dst[(((size_t)(bidx * NH + hh)) * SS + s) * HD + d0] = o;
    }
}

// ---------------------------------------------------------------------------
// Kernel 2: attention with relu^2 "softmax" (elementwise -> pure streaming).
// Each block: one (b,h), 64 queries. Loop over K/V tiles of 64 keys.
//   S = (Q K^T) * scale + mask ; P = relu(S)^2 ; ctx += P V
// ---------------------------------------------------------------------------
__global__ __launch_bounds__(256) void attn_kernel(
    const float* __restrict__ mask, float* __restrict__ out)
{
    __shared__ float qT[64][64];   // [d][q]
    __shared__ float kv[64][64];   // K phase: [d][k] ; V phase: [k][d]
    __shared__ float ps[64][64];   // [q][k]

    const int tid = threadIdx.x;
    const int tx = tid & 15;
    const int ty = tid >> 4;

    const int bh = blockIdx.y;          // 0..63
    const int b = bh >> 4;
    const int h = bh & 15;
    const int qBase = blockIdx.x * 64;

    const float* qg = g_q + (size_t)bh * SS * HD;
    const float* kg = g_k + (size_t)bh * SS * HD;
    const float* vg = g_v + (size_t)bh * SS * HD;

    const int lr = tid >> 2;        // 0..63
    const int lc = tid & 3;         // 0..3

    const float scale = 0.125f;     // 1/sqrt(64)

    // Load Q tile transposed: qT[d][q]
    #pragma unroll
    for (int c = 0; c < 4; c++) {
        int d0 = lc * 4 + c * 16;
        float4 a = *(const float4*)&qg[(size_t)(qBase + lr) * HD + d0];
        qT[d0 + 0][lr] = a.x; qT[d0 + 1][lr] = a.y;
        qT[d0 + 2][lr] = a.z; qT[d0 + 3][lr] = a.w;
    }

    float acc[4][4] = {};

    for (int kb = 0; kb < SS; kb += 64) {
        __syncthreads();  // prev-iter V reads done (and qT visible on iter 0)

        // Load K tile transposed: kv[d][k]
        #pragma unroll
        for (int c = 0; c < 4; c++) {
            int d0 = lc * 4 + c * 16;
            float4 a = *(const float4*)&kg[(size_t)(kb + lr) * HD + d0];
            kv[d0 + 0][lr] = a.x; kv[d0 + 1][lr] = a.y;
            kv[d0 + 2][lr] = a.z; kv[d0 + 3][lr] = a.w;
        }
        __syncthreads();

        // S tile: sacc[i][j] = sum_d q[qi][d] * k[kj][d]
        float sacc[4][4] = {};
        #pragma unroll
        for (int d = 0; d < 64; d++) {
            float4 qv = *(const float4*)&qT[d][ty * 4];
            float4 kx = *(const float4*)&kv[d][tx * 4];
            float aa[4] = {qv.x, qv.y, qv.z, qv.w};
            float bb[4] = {kx.x, kx.y, kx.z, kx.w};
            #pragma unroll
            for (int i = 0; i < 4; i++)
                #pragma unroll
                for (int j = 0; j < 4; j++)
                    sacc[i][j] += aa[i] * bb[j];
        }

        // mask + relu^2, stage P tile to smem as [q][k]
        float m0 = mask[b * SS + kb + tx * 4 + 0];
        float m1 = mask[b * SS + kb + tx * 4 + 1];
        float m2 = mask[b * SS + kb + tx * 4 + 2];
        float m3 = mask[b * SS + kb + tx * 4 + 3];
        #pragma unroll
        for (int i = 0; i < 4; i++) {
            float v0 = fmaxf(sacc[i][0] * scale + m0, 0.0f);
            float v1 = fmaxf(sacc[i][1] * scale + m1, 0.0f);
            float v2 = fmaxf(sacc[i][2] * scale + m2, 0.0f);
            float v3 = fmaxf(sacc[i][3] * scale + m3, 0.0f);
            float4 pv = make_float4(v0 * v0, v1 * v1, v2 * v2, v3 * v3);
            *(float4*)&ps[ty * 4 + i][tx * 4] = pv;
        }
        __syncthreads();  // ps written; kv (K) no longer needed

        // Load V tile: kv[k][d] (natural layout)
        #pragma unroll
        for (int c = 0; c < 4; c++) {
            int d0 = lc * 4 + c * 16;
            *(float4*)&kv[lr][d0] =
                *(const float4*)&vg[(size_t)(kb + lr) * HD + d0];
        }
        __syncthreads();

        // ctx += P @ V : acc[i][j] += ps[qi][kk] * V[kk][dj]
        #pragma unroll
        for (int kk = 0; kk < 64; kk++) {
            float pr[4];
            #pragma unroll
            for (int i = 0; i < 4; i++) pr[i] = ps[ty * 4 + i][kk];
            float4 vv = *(const float4*)&kv[kk][tx * 4];
            float bb[4] = {vv.x, vv.y, vv.z, vv.w};
            #pragma unroll
            for (int i = 0; i < 4; i++)
                #pragma unroll
                for (int j = 0; j < 4; j++)
                    acc[i][j] += pr[i] * bb[j];
        }
    }

    // Write context: out[b][s][h*64 + d]
    #pragma unroll
    for (int i = 0; i < 4; i++) {
        int s = qBase + ty * 4 + i;
        float4 o = make_float4(acc[i][0], acc[i][1], acc[i][2], acc[i][3]);
        *(float4*)&out[((size_t)(b * SS + s)) * DM + h * HD + tx * 4] = o;
    }
}

extern "C" void kernel_launch(void* const* d_in, const int* in_sizes, int n_in,
                              void* d_out, int out_size)
{
    const float* x    = (const float*)d_in[0];
    const float* mask = (const float*)d_in[1];
    const float* Wq   = (const float*)d_in[2];
    const float* bq   = (const float*)d_in[3];
    const float* Wk   = (const float*)d_in[4];
    const float* bk   = (const float*)d_in[5];
    const float* Wv   = (const float*)d_in[6];
    const float* bv   = (const float*)d_in[7];
    float* out = (float*)d_out;

    // QKV projections: combined 3072-wide output, 64x64 tiles.
    qkv_kernel<<<dim3(3 * DM / 64, (BB * SS) / 64), 256>>>(
        x, Wq, bq, Wk, bk, Wv, bv);

    // Attention: 32 query-tiles x 64 (b,h) pairs.
    attn_kernel<<<dim3(SS / 64, BB * NH), 256>>>(mask, out);
}

// round 2
// speedup vs baseline: 2.5498x; 2.5498x over previous
#include <cuda_runtime.h>

#define BB 4
#define SS 2048
#define NH 16
#define HD 64
#define DM 1024

// Scratch for Q/K/V in [B, H, S, hd] layout (device globals: allocation-free).
__device__ __align__(16) float g_q[BB * NH * SS * HD];
__device__ __align__(16) float g_k[BB * NH * SS * HD];
__device__ __align__(16) float g_v[BB * NH * SS * HD];

__device__ __forceinline__ unsigned f2tf(float x) {
    unsigned u;
    asm("cvt.rna.tf32.f32 %0, %1;" : "=r"(u) : "f"(x));
    return u;
}

__device__ __forceinline__ void mma_tf32(float* c, const unsigned* a, const unsigned* b) {
    asm volatile(
        "mma.sync.aligned.m16n8k8.row.col.f32.tf32.tf32.f32 "
        "{%0,%1,%2,%3}, {%4,%5,%6,%7}, {%8,%9}, {%0,%1,%2,%3};"
        : "+f"(c[0]), "+f"(c[1]), "+f"(c[2]), "+f"(c[3])
        : "r"(a[0]), "r"(a[1]), "r"(a[2]), "r"(a[3]), "r"(b[0]), "r"(b[1]));
}

// ---------------------------------------------------------------------------
// Kernel 1: fused QKV projection with tf32 MMA.
// C = X @ W^T + b. Block tile 128(m) x 64(n), 8 warps (4m x 2n), 32x32/warp.
// ---------------------------------------------------------------------------
__global__ __launch_bounds__(256) void qkv_kernel(
    const float* __restrict__ x,
    const float* __restrict__ Wq, const float* __restrict__ bq,
    const float* __restrict__ Wk, const float* __restrict__ bk,
    const float* __restrict__ Wv, const float* __restrict__ bv)
{
    __shared__ unsigned As[128 * 36];   // A tile [row][k], stride 36 (conflict-free)
    __shared__ unsigned Bs[64 * 36];    // W tile [n][k]

    const int tid = threadIdx.x;
    const int lane = tid & 31;
    const int w = tid >> 5;
    const int wm = w & 3;            // 0..3 -> m offset 32*wm
    const int wn = w >> 2;           // 0..1 -> n offset 32*wn
    const int mRow0 = wm * 32;
    const int nCol0 = wn * 32;

    const int rowBase = blockIdx.y * 128;     // token rows
    const int colBase = blockIdx.x * 64;      // combined cols [0,3072)
    const int mat = colBase / DM;             // 0=Q 1=K 2=V
    const int colInMat = colBase % DM;
    const int head = colInMat / HD;

    const float* W    = (mat == 0) ? Wq : (mat == 1) ? Wk : Wv;
    const float* bias = (mat == 0) ? bq : (mat == 1) ? bk : bv;
    float*       dst  = (mat == 0) ? g_q : (mat == 1) ? g_k : g_v;

    float acc[2][4][4] = {};

    for (int kt = 0; kt < DM; kt += 32) {
        // Load A tile 128x32: 4 float4 per thread, coalesced.
        #pragma unroll
        for (int j = 0; j < 4; j++) {
            int idx = tid + j * 256;
            int row = idx >> 3;
            int c4 = (idx & 7) * 4;
            float4 a = *(const float4*)&x[(size_t)(rowBase + row) * DM + kt + c4];
            unsigned* p = &As[row * 36 + c4];
            p[0] = f2tf(a.x); p[1] = f2tf(a.y); p[2] = f2tf(a.z); p[3] = f2tf(a.w);
        }
        // Load B tile 64x32: 2 float4 per thread.
        #pragma unroll
        for (int j = 0; j < 2; j++) {
            int idx = tid + j * 256;
            int row = idx >> 3;
            int c4 = (idx & 7) * 4;
            float4 bvv = *(const float4*)&W[(size_t)(colInMat + row) * DM + kt + c4];
            unsigned* p = &Bs[row * 36 + c4];
            p[0] = f2tf(bvv.x); p[1] = f2tf(bvv.y); p[2] = f2tf(bvv.z); p[3] = f2tf(bvv.w);
        }
        __syncthreads();

        #pragma unroll
        for (int kk = 0; kk < 4; kk++) {
            const int col = kk * 8 + (lane & 3);
            unsigned a[2][4];
            #pragma unroll
            for (int mi = 0; mi < 2; mi++) {
                int r = mRow0 + mi * 16 + (lane >> 2);
                a[mi][0] = As[r * 36 + col];
                a[mi][1] = As[(r + 8) * 36 + col];
                a[mi][2] = As[r * 36 + col + 4];
                a[mi][3] = As[(r + 8) * 36 + col + 4];
            }
            #pragma unroll
            for (int ni = 0; ni < 4; ni++) {
                int n0 = nCol0 + ni * 8 + (lane >> 2);
                unsigned b[2];
                b[0] = Bs[n0 * 36 + col];
                b[1] = Bs[n0 * 36 + col + 4];
                mma_tf32(acc[0][ni], a[0], b);
                mma_tf32(acc[1][ni], a[1], b);
            }
        }
        __syncthreads();
    }

    // Epilogue: bias + scatter into [B,H,S,hd].
    #pragma unroll
    for (int mi = 0; mi < 2; mi++) {
        #pragma unroll
        for (int ni = 0; ni < 4; ni++) {
            int d = nCol0 + ni * 8 + 2 * (lane & 3);
            float b0 = bias[colInMat + d];
            float b1 = bias[colInMat + d + 1];
            #pragma unroll
            for (int half = 0; half < 2; half++) {
                int token = rowBase + mRow0 + mi * 16 + (lane >> 2) + half * 8;
                int bidx = token >> 11;
                int s = token & (SS - 1);
                float2 o;
                o.x = acc[mi][ni][half * 2 + 0] + b0;
                o.y = acc[mi][ni][half * 2 + 1] + b1;
                *(float2*)&dst[(((size_t)(bidx * NH + head)) * SS + s) * HD + d] = o;
            }
        }
    }
}

// ---------------------------------------------------------------------------
// Kernel 2: attention with relu^2 "softmax", tf32 MMA.
// Block: one (b,h), 64 queries. 8 warps: wm=w&3 -> 16 query rows,
// wn=w>>2 -> key-half (S phase) / dim-half (PV phase).
// ---------------------------------------------------------------------------
__global__ __launch_bounds__(256) void attn_kernel(
    const float* __restrict__ mask, float* __restrict__ out)
{
    __shared__ unsigned kvs[64 * 68];   // K tile [key][d] then V^T tile [d][key]
    __shared__ unsigned ps[64 * 68];    // P tile [q][key], tf32

    const int tid = threadIdx.x;
    const int lane = tid & 31;
    const int w = tid >> 5;
    const int wm = w & 3;           // query-row tile (16 rows)
    const int wn = w >> 2;          // half selector (32 wide)
    const int qRow0 = wm * 16;

    const int bh = blockIdx.y;          // 0..63
    const int b = bh >> 4;
    const int h = bh & 15;
    const int qBase = blockIdx.x * 64;

    const float* qg = g_q + (size_t)bh * SS * HD;
    const float* kg = g_k + (size_t)bh * SS * HD;
    const float* vg = g_v + (size_t)bh * SS * HD;
    const float* maskrow = mask + b * SS;

    const float scale = 0.125f;     // 1/sqrt(64)

    // Hoist Q fragments (reused for all 32 key tiles).
    unsigned a_q[8][4];
    {
        int r0 = qBase + qRow0 + (lane >> 2);
        int r1 = r0 + 8;
        #pragma unroll
        for (int kk = 0; kk < 8; kk++) {
            int col = kk * 8 + (lane & 3);
            a_q[kk][0] = f2tf(qg[(size_t)r0 * HD + col]);
            a_q[kk][1] = f2tf(qg[(size_t)r1 * HD + col]);
            a_q[kk][2] = f2tf(qg[(size_t)r0 * HD + col + 4]);
            a_q[kk][3] = f2tf(qg[(size_t)r1 * HD + col + 4]);
        }
    }

    float ctx[4][4] = {};   // 16 q-rows x 32 dims per warp

    for (int kb = 0; kb < SS; kb += 64) {
        __syncthreads();  // prev-iter V reads done

        // Load K tile -> kvs[key][d], 4 float4 per thread, coalesced.
        #pragma unroll
        for (int j = 0; j < 4; j++) {
            int idx = tid + j * 256;
            int key = idx >> 4;
            int c4 = (idx & 15) * 4;
            float4 kv4 = *(const float4*)&kg[(size_t)(kb + key) * HD + c4];
            unsigned* p = &kvs[key * 68 + c4];
            p[0] = f2tf(kv4.x); p[1] = f2tf(kv4.y); p[2] = f2tf(kv4.z); p[3] = f2tf(kv4.w);
        }
        __syncthreads();

        // S = Q K^T over this warp's 16 q-rows x 32 key-cols.
        float s[4][4] = {};
        #pragma unroll
        for (int kk = 0; kk < 8; kk++) {
            int col = kk * 8 + (lane & 3);
            #pragma unroll
            for (int ni = 0; ni < 4; ni++) {
                int n0 = wn * 32 + ni * 8 + (lane >> 2);
                unsigned bf[2];
                bf[0] = kvs[n0 * 68 + col];
                bf[1] = kvs[n0 * 68 + col + 4];
                mma_tf32(s[ni], a_q[kk], bf);
            }
        }

        // P = relu(S*scale + mask)^2 -> ps (tf32).
        #pragma unroll
        for (int ni = 0; ni < 4; ni++) {
            int cl = wn * 32 + ni * 8 + 2 * (lane & 3);     // local key col
            float2 m2 = *(const float2*)&maskrow[kb + cl];
            int r0 = qRow0 + (lane >> 2);
            #pragma unroll
            for (int half = 0; half < 2; half++) {
                int r = r0 + half * 8;
                float p0 = fmaxf(s[ni][half * 2 + 0] * scale + m2.x, 0.0f);
                float p1 = fmaxf(s[ni][half * 2 + 1] * scale + m2.y, 0.0f);
                uint2 pv;
                pv.x = f2tf(p0 * p0);
                pv.y = f2tf(p1 * p1);
                *(uint2*)&ps[r * 68 + cl] = pv;
            }
        }
        __syncthreads();  // all P written; all K reads done

        // Load V tile transposed -> kvs[d][key].
        #pragma unroll
        for (int j = 0; j < 4; j++) {
            int idx = tid + j * 256;
            int key = idx >> 4;
            int c4 = (idx & 15) * 4;
            float4 vv = *(const float4*)&vg[(size_t)(kb + key) * HD + c4];
            kvs[(c4 + 0) * 68 + key] = f2tf(vv.x);
            kvs[(c4 + 1) * 68 + key] = f2tf(vv.y);
            kvs[(c4 + 2) * 68 + key] = f2tf(vv.z);
            kvs[(c4 + 3) * 68 + key] = f2tf(vv.w);
        }
        __syncthreads();

        // ctx += P @ V : A = ps rows (this warp's 16 q-rows), k = 64 keys;
        // B = kvs[d][key] (n = dim, k = key).
        #pragma unroll
        for (int kk = 0; kk < 8; kk++) {
            int col = kk * 8 + (lane & 3);
            int r0 = qRow0 + (lane >> 2);
            unsigned a[4];
            a[0] = ps[r0 * 68 + col];
            a[1] = ps[(r0 + 8) * 68 + col];
            a[2] = ps[r0 * 68 + col + 4];
            a[3] = ps[(r0 + 8) * 68 + col + 4];
            #pragma unroll
            for (int ti = 0; ti < 4; ti++) {
                int n0 = wn * 32 + ti * 8 + (lane >> 2);
                unsigned bf[2];
                bf[0] = kvs[n0 * 68 + col];
                bf[1] = kvs[n0 * 68 + col + 4];
                mma_tf32(ctx[ti], a, bf);
            }
        }
    }

    // Write context: out[b][s][h*64 + d].
    #pragma unroll
    for (int ti = 0; ti < 4; ti++) {
        int d = wn * 32 + ti * 8 + 2 * (lane & 3);
        #pragma unroll
        for (int half = 0; half < 2; half++) {
            int s = qBase + qRow0 + (lane >> 2) + half * 8;
            float2 o;
            o.x = ctx[ti][half * 2 + 0];
            o.y = ctx[ti][half * 2 + 1];
            *(float2*)&out[((size_t)(b * SS + s)) * DM + h * HD + d] = o;
        }
    }
}

extern "C" void kernel_launch(void* const* d_in, const int* in_sizes, int n_in,
                              void* d_out, int out_size)
{
    const float* x    = (const float*)d_in[0];
    const float* mask = (const float*)d_in[1];
    const float* Wq   = (const float*)d_in[2];
    const float* bq   = (const float*)d_in[3];
    const float* Wk   = (const float*)d_in[4];
    const float* bk   = (const float*)d_in[5];
    const float* Wv   = (const float*)d_in[6];
    const float* bv   = (const float*)d_in[7];
    float* out = (float*)d_out;

    // QKV projections: combined 3072-wide output, 128x64 tiles.
    qkv_kernel<<<dim3(3 * DM / 64, (BB * SS) / 128), 256>>>(
        x, Wq, bq, Wk, bk, Wv, bv);

    // Attention: 32 query-tiles x 64 (b,h) pairs.
    attn_kernel<<<dim3(SS / 64, BB * NH), 256>>>(mask, out);
}

// round 3
// speedup vs baseline: 2.9671x; 1.1637x over previous
#include <cuda_runtime.h>

#define BB 4
#define SS 2048
#define NH 16
#define HD 64
#define DM 1024

// Scratch for Q/K/V in [B, H, S, hd] layout (device globals: allocation-free).
__device__ __align__(16) float g_q[BB * NH * SS * HD];
__device__ __align__(16) float g_k[BB * NH * SS * HD];
__device__ __align__(16) float g_v[BB * NH * SS * HD];

__device__ __forceinline__ unsigned f2tf(float x) {
    unsigned u;
    asm("cvt.rna.tf32.f32 %0, %1;" : "=r"(u) : "f"(x));
    return u;
}

__device__ __forceinline__ void mma_tf32(float* c, const unsigned* a, const unsigned* b) {
    asm volatile(
        "mma.sync.aligned.m16n8k8.row.col.f32.tf32.tf32.f32 "
        "{%0,%1,%2,%3}, {%4,%5,%6,%7}, {%8,%9}, {%0,%1,%2,%3};"
        : "+f"(c[0]), "+f"(c[1]), "+f"(c[2]), "+f"(c[3])
        : "r"(a[0]), "r"(a[1]), "r"(a[2]), "r"(a[3]), "r"(b[0]), "r"(b[1]));
}

// ---------------------------------------------------------------------------
// Kernel 1: fused QKV projection with tf32 MMA (unchanged from R2).
// ---------------------------------------------------------------------------
__global__ __launch_bounds__(256) void qkv_kernel(
    const float* __restrict__ x,
    const float* __restrict__ Wq, const float* __restrict__ bq,
    const float* __restrict__ Wk, const float* __restrict__ bk,
    const float* __restrict__ Wv, const float* __restrict__ bv)
{
    __shared__ unsigned As[128 * 36];
    __shared__ unsigned Bs[64 * 36];

    const int tid = threadIdx.x;
    const int lane = tid & 31;
    const int w = tid >> 5;
    const int wm = w & 3;
    const int wn = w >> 2;
    const int mRow0 = wm * 32;
    const int nCol0 = wn * 32;

    const int rowBase = blockIdx.y * 128;
    const int colBase = blockIdx.x * 64;
    const int mat = colBase / DM;
    const int colInMat = colBase % DM;
    const int head = colInMat / HD;

    const float* W    = (mat == 0) ? Wq : (mat == 1) ? Wk : Wv;
    const float* bias = (mat == 0) ? bq : (mat == 1) ? bk : bv;
    float*       dst  = (mat == 0) ? g_q : (mat == 1) ? g_k : g_v;

    float acc[2][4][4] = {};

    for (int kt = 0; kt < DM; kt += 32) {
        #pragma unroll
        for (int j = 0; j < 4; j++) {
            int idx = tid + j * 256;
            int row = idx >> 3;
            int c4 = (idx & 7) * 4;
            float4 a = *(const float4*)&x[(size_t)(rowBase + row) * DM + kt + c4];
            unsigned* p = &As[row * 36 + c4];
            p[0] = f2tf(a.x); p[1] = f2tf(a.y); p[2] = f2tf(a.z); p[3] = f2tf(a.w);
        }
        #pragma unroll
        for (int j = 0; j < 2; j++) {
            int idx = tid + j * 256;
            int row = idx >> 3;
            int c4 = (idx & 7) * 4;
            float4 bvv = *(const float4*)&W[(size_t)(colInMat + row) * DM + kt + c4];
            unsigned* p = &Bs[row * 36 + c4];
            p[0] = f2tf(bvv.x); p[1] = f2tf(bvv.y); p[2] = f2tf(bvv.z); p[3] = f2tf(bvv.w);
        }
        __syncthreads();

        #pragma unroll
        for (int kk = 0; kk < 4; kk++) {
            const int col = kk * 8 + (lane & 3);
            unsigned a[2][4];
            #pragma unroll
            for (int mi = 0; mi < 2; mi++) {
                int r = mRow0 + mi * 16 + (lane >> 2);
                a[mi][0] = As[r * 36 + col];
                a[mi][1] = As[(r + 8) * 36 + col];
                a[mi][2] = As[r * 36 + col + 4];
                a[mi][3] = As[(r + 8) * 36 + col + 4];
            }
            #pragma unroll
            for (int ni = 0; ni < 4; ni++) {
                int n0 = nCol0 + ni * 8 + (lane >> 2);
                unsigned b[2];
                b[0] = Bs[n0 * 36 + col];
                b[1] = Bs[n0 * 36 + col + 4];
                mma_tf32(acc[0][ni], a[0], b);
                mma_tf32(acc[1][ni], a[1], b);
            }
        }
        __syncthreads();
    }

    #pragma unroll
    for (int mi = 0; mi < 2; mi++) {
        #pragma unroll
        for (int ni = 0; ni < 4; ni++) {
            int d = nCol0 + ni * 8 + 2 * (lane & 3);
            float b0 = bias[colInMat + d];
            float b1 = bias[colInMat + d + 1];
            #pragma unroll
            for (int half = 0; half < 2; half++) {
                int token = rowBase + mRow0 + mi * 16 + (lane >> 2) + half * 8;
                int bidx = token >> 11;
                int s = token & (SS - 1);
                float2 o;
                o.x = acc[mi][ni][half * 2 + 0] + b0;
                o.y = acc[mi][ni][half * 2 + 1] + b1;
                *(float2*)&dst[(((size_t)(bidx * NH + head)) * SS + s) * HD + d] = o;
            }
        }
    }
}

// ---------------------------------------------------------------------------
// Kernel 2: attention, tf32 MMA, vectorized fragment traffic.
// Layouts (dynamic smem, stride 72 words):
//   ks[key][P(d)]   : pair-permuted along d  -> S-phase B frags = LDS.64
//   ps[q][P(key)]   : pair-permuted along key-> PV A frags = LDS.64
//   vs[key][d]      : natural                -> STS.128 stores, scalar B reads
//     (stride 72: PV B read banks = 8t + (lane>>2) -> conflict-free)
// ---------------------------------------------------------------------------
#define ATTN_SMEM_BYTES (3 * 64 * 72 * 4)

__global__ __launch_bounds__(256) void attn_kernel(
    const float* __restrict__ mask, float* __restrict__ out)
{
    extern __shared__ unsigned smem[];
    unsigned* ks = smem;                 // 64*72
    unsigned* ps = smem + 64 * 72;       // 64*72
    unsigned* vs = smem + 2 * 64 * 72;   // 64*72

    const int tid = threadIdx.x;
    const int lane = tid & 31;
    const int w = tid >> 5;
    const int wm = w & 3;
    const int wn = w >> 2;
    const int qRow0 = wm * 16;
    const int t = lane & 3;
    const int qr = lane >> 2;

    const int bh = blockIdx.y;
    const int b = bh >> 4;
    const int h = bh & 15;
    const int qBase = blockIdx.x * 64;

    const float* qg = g_q + (size_t)bh * SS * HD;
    const float* kg = g_k + (size_t)bh * SS * HD;
    const float* vg = g_v + (size_t)bh * SS * HD;
    const float* maskrow = mask + b * SS;

    const float scale = 0.125f;

    // Hoist Q fragments (reused for all 32 key tiles).
    unsigned a_q[8][4];
    {
        int r0 = qBase + qRow0 + qr;
        int r1 = r0 + 8;
        #pragma unroll
        for (int kk = 0; kk < 8; kk++) {
            int col = kk * 8 + t;
            a_q[kk][0] = f2tf(qg[(size_t)r0 * HD + col]);
            a_q[kk][1] = f2tf(qg[(size_t)r1 * HD + col]);
            a_q[kk][2] = f2tf(qg[(size_t)r0 * HD + col + 4]);
            a_q[kk][3] = f2tf(qg[(size_t)r1 * HD + col + 4]);
        }
    }

    // Pair-permute offsets for P writes (logical cols 2t, 2t+1).
    const int c0 = 2 * t;
    const int e0 = ((c0 & 3) << 1) | ((c0 >> 2) & 1);
    const int e1 = (((c0 + 1) & 3) << 1) | (((c0 + 1) >> 2) & 1);

    float ctx[4][4] = {};

    for (int kb = 0; kb < SS; kb += 64) {
        __syncthreads();  // prior-iter reads of ks/vs/ps complete

        // Load K tile -> ks[key][P(d)] ; V tile -> vs[key][d].
        #pragma unroll
        for (int j = 0; j < 4; j++) {
            int idx = tid + j * 256;
            int key = idx >> 4;
            int c4 = (idx & 15) * 4;
            float4 kd = *(const float4*)&kg[(size_t)(kb + key) * HD + c4];
            int kbase = (c4 & ~7) | ((c4 >> 2) & 1);
            unsigned* kp = &ks[key * 72 + kbase];
            kp[0] = f2tf(kd.x); kp[2] = f2tf(kd.y);
            kp[4] = f2tf(kd.z); kp[6] = f2tf(kd.w);

            float4 vd = *(const float4*)&vg[(size_t)(kb + key) * HD + c4];
            uint4 vu;
            vu.x = f2tf(vd.x); vu.y = f2tf(vd.y);
            vu.z = f2tf(vd.z); vu.w = f2tf(vd.w);
            *(uint4*)&vs[key * 72 + c4] = vu;
        }
        __syncthreads();

        // S = Q K^T over this warp's 16 q-rows x 32 key-cols.
        float s[4][4] = {};
        #pragma unroll
        for (int kk = 0; kk < 8; kk++) {
            #pragma unroll
            for (int ni = 0; ni < 4; ni++) {
                int n0 = wn * 32 + ni * 8 + qr;
                uint2 bu = *(const uint2*)&ks[n0 * 72 + kk * 8 + 2 * t];
                unsigned bf[2] = {bu.x, bu.y};
                mma_tf32(s[ni], a_q[kk], bf);
            }
        }

        // P = relu(S*scale + mask)^2 -> ps[q][P(key)] (tf32).
        #pragma unroll
        for (int ni = 0; ni < 4; ni++) {
            int basec = wn * 32 + ni * 8;
            float2 m2 = *(const float2*)&maskrow[kb + basec + c0];
            #pragma unroll
            for (int half = 0; half < 2; half++) {
                int r = qRow0 + qr + half * 8;
                float p0 = fmaxf(s[ni][half * 2 + 0] * scale + m2.x, 0.0f);
                float p1 = fmaxf(s[ni][half * 2 + 1] * scale + m2.y, 0.0f);
                ps[r * 72 + basec + e0] = f2tf(p0 * p0);
                ps[r * 72 + basec + e1] = f2tf(p1 * p1);
            }
        }
        __syncthreads();  // all P written; ks reads done

        // ctx += P @ V.  A from ps (LDS.64 pairs), B from vs (natural).
        #pragma unroll
        for (int kk = 0; kk < 8; kk++) {
            int r0 = qRow0 + qr;
            uint2 lo = *(const uint2*)&ps[r0 * 72 + kk * 8 + 2 * t];
            uint2 hi = *(const uint2*)&ps[(r0 + 8) * 72 + kk * 8 + 2 * t];
            unsigned a[4] = {lo.x, hi.x, lo.y, hi.y};
            #pragma unroll
            for (int ti = 0; ti < 4; ti++) {
                int n0 = wn * 32 + ti * 8 + qr;
                unsigned bf[2];
                bf[0] = vs[(kk * 8 + t) * 72 + n0];
                bf[1] = vs[(kk * 8 + t + 4) * 72 + n0];
                mma_tf32(ctx[ti], a, bf);
            }
        }
    }

    // Write context: out[b][s][h*64 + d].
    #pragma unroll
    for (int ti = 0; ti < 4; ti++) {
        int d = wn * 32 + ti * 8 + c0;
        #pragma unroll
        for (int half = 0; half < 2; half++) {
            int s = qBase + qRow0 + qr + half * 8;
            float2 o;
            o.x = ctx[ti][half * 2 + 0];
            o.y = ctx[ti][half * 2 + 1];
            *(float2*)&out[((size_t)(b * SS + s)) * DM + h * HD + d] = o;
        }
    }
}

extern "C" void kernel_launch(void* const* d_in, const int* in_sizes, int n_in,
                              void* d_out, int out_size)
{
    const float* x    = (const float*)d_in[0];
    const float* mask = (const float*)d_in[1];
    const float* Wq   = (const float*)d_in[2];
    const float* bq   = (const float*)d_in[3];
    const float* Wk   = (const float*)d_in[4];
    const float* bk   = (const float*)d_in[5];
    const float* Wv   = (const float*)d_in[6];
    const float* bv   = (const float*)d_in[7];
    float* out = (float*)d_out;

    cudaFuncSetAttribute(attn_kernel,
                         cudaFuncAttributeMaxDynamicSharedMemorySize,
                         ATTN_SMEM_BYTES);

    qkv_kernel<<<dim3(3 * DM / 64, (BB * SS) / 128), 256>>>(
        x, Wq, bq, Wk, bk, Wv, bv);

    attn_kernel<<<dim3(SS / 64, BB * NH), 256, ATTN_SMEM_BYTES>>>(mask, out);
}